// round 16
// baseline (speedup 1.0000x reference)
#include <cuda_runtime.h>

// Problem constants
#define IN_DIM  8192
#define OUT_DIM 8192

// Partial-kernel tiling: 128 threads x float2 = 256 cols/block, 256 row chunks
#define P_THREADS 128
#define VEC 2
#define COLS_PER_BLOCK (P_THREADS * VEC)            // 256
#define N_STRIPES      (OUT_DIM / COLS_PER_BLOCK)   // 32
#define N_ROW_CHUNKS   256
#define ROWS_PER_CHUNK (IN_DIM / N_ROW_CHUNKS)      // 32

// Init: seed both output halves with bias (out is poisoned each replay)
#define I_THREADS 256
__global__ __launch_bounds__(I_THREADS)
void ibp_init_kernel(const float* __restrict__ bias,
                     float* __restrict__ out) {
    const int i = blockIdx.x * I_THREADS + threadIdx.x;   // [0, 2048) float4s
    float4 b = reinterpret_cast<const float4*>(bias)[i];
    reinterpret_cast<float4*>(out)[i] = b;                // bound_l base
    reinterpret_cast<float4*>(out + OUT_DIM)[i] = b;      // bound_u base
#if __CUDA_ARCH__ >= 900
    cudaTriggerProgrammaticLaunchCompletion();
#endif
}

__device__ __forceinline__ void red_add_v2(float* p, float x, float y) {
    asm volatile("red.global.add.v2.f32 [%0], {%1, %2};"
                 :: "l"(p), "f"(x), "f"(y) : "memory");
}

__global__ __launch_bounds__(P_THREADS)
void ibp_partial_kernel(const float* __restrict__ l,
                        const float* __restrict__ u,
                        const float* __restrict__ w,
                        float* __restrict__ out) {
    __shared__ float sc[ROWS_PER_CHUNK];
    __shared__ float sr[ROWS_PER_CHUNK];

    const int col0 = blockIdx.x * COLS_PER_BLOCK + threadIdx.x * VEC;
    const int row0 = blockIdx.y * ROWS_PER_CHUNK;

    if (threadIdx.x < ROWS_PER_CHUNK) {
        int i = threadIdx.x;
        float lv = l[row0 + i];
        float uv = u[row0 + i];
        sc[i] = 0.5f * (lv + uv);
        sr[i] = 0.5f * (uv - lv);
    }

#if __CUDA_ARCH__ >= 900
    // PDL: wait for the init kernel's bias-seeding stores before touching out.
    cudaGridDependencySynchronize();
#endif
    __syncthreads();

    float s1x = 0.f, s1y = 0.f;
    float s2x = 0.f, s2y = 0.f;

    const float2* __restrict__ wp =
        reinterpret_cast<const float2*>(w + (size_t)row0 * OUT_DIM + col0);
    const size_t rstride = OUT_DIM / 2;

    #pragma unroll 16
    for (int i = 0; i < ROWS_PER_CHUNK; i++) {
        float2 wv = __ldcs(&wp[(size_t)i * rstride]);   // stream, evict-first
        float c = sc[i];
        float r = sr[i];
        s1x = fmaf(c, wv.x, s1x);
        s1y = fmaf(c, wv.y, s1y);
        s2x = fmaf(r, fabsf(wv.x), s2x);
        s2y = fmaf(r, fabsf(wv.y), s2y);
    }

    // Accumulate directly into the (bias-seeded, L2-resident) outputs.
    red_add_v2(out + col0,           s1x - s2x, s1y - s2y);   // bound_l
    red_add_v2(out + OUT_DIM + col0, s1x + s2x, s1y + s2y);   // bound_u
}

extern "C" void kernel_launch(void* const* d_in, const int* in_sizes, int n_in,
                              void* d_out, int out_size) {
    const float* l    = (const float*)d_in[0];
    const float* u    = (const float*)d_in[1];
    const float* w    = (const float*)d_in[2];
    const float* bias = (const float*)d_in[3];
    float* out = (float*)d_out;

    // Primary: bias seeding (8 CTAs)
    ibp_init_kernel<<<(OUT_DIM / 4) / I_THREADS, I_THREADS>>>(bias, out);

    // Secondary: main stream with programmatic stream serialization.
    cudaLaunchConfig_t cfg = {};
    cfg.gridDim  = dim3(N_STRIPES, N_ROW_CHUNKS);   // (32, 256) = 8192 CTAs
    cfg.blockDim = dim3(P_THREADS);
    cfg.dynamicSmemBytes = 0;
    cfg.stream = 0;
    cudaLaunchAttribute attrs[1];
    attrs[0].id = cudaLaunchAttributeProgrammaticStreamSerialization;
    attrs[0].val.programmaticStreamSerializationAllowed = 1;
    cfg.attrs = attrs;
    cfg.numAttrs = 1;
    cudaLaunchKernelEx(&cfg, ibp_partial_kernel, l, u, w, out);
}